// round 2
// baseline (speedup 1.0000x reference)
#include <cuda_runtime.h>

// Problem constants
#define BATCH 4
#define SEQ   2048
#define DIM   1024
#define SCALE 0.03125f   // 1024^-0.5

// Tile config
#define BM 128
#define BN 128
#define BK 8
#define TM 8
#define TN 8
#define NTHREADS 256

// Scratch (device globals: allocation-free rule)
static __device__ float g_q[BATCH * SEQ * DIM];
static __device__ float g_k[BATCH * SEQ * DIM];
static __device__ float g_v[BATCH * SEQ * DIM];
static __device__ float g_s[(size_t)BATCH * SEQ * SEQ];

// ---------------------------------------------------------------------------
// TN GEMM tile: C[m,n] = alpha * sum_k A[m,k] * B[n,k]
// A: [M,K] row-major (K contiguous). B: [N,K] row-major (K contiguous).
// ---------------------------------------------------------------------------
__device__ __forceinline__ void gemm_tn_tile(
    const float* __restrict__ A, const float* __restrict__ B,
    float* __restrict__ C,
    int N, int K, int Klim, float alpha, int bm, int bn)
{
    __shared__ float As[BK][BM];
    __shared__ float Bs[BK][BN];

    const int tid = threadIdx.x;
    const int tx = tid % (BN / TN);   // 0..15
    const int ty = tid / (BN / TN);   // 0..15
    const int lr = tid / 2;           // load row 0..127
    const int lc = (tid % 2) * 4;     // load k-offset 0 or 4

    float acc[TM][TN];
#pragma unroll
    for (int i = 0; i < TM; i++)
#pragma unroll
        for (int j = 0; j < TN; j++) acc[i][j] = 0.0f;

    const float* Aptr = A + (long)(bm * BM + lr) * K + lc;
    const float* Bptr = B + (long)(bn * BN + lr) * K + lc;

    for (int k0 = 0; k0 < Klim; k0 += BK) {
        float4 a4 = *(const float4*)(Aptr + k0);
        float4 b4 = *(const float4*)(Bptr + k0);
        As[lc + 0][lr] = a4.x; As[lc + 1][lr] = a4.y;
        As[lc + 2][lr] = a4.z; As[lc + 3][lr] = a4.w;
        Bs[lc + 0][lr] = b4.x; Bs[lc + 1][lr] = b4.y;
        Bs[lc + 2][lr] = b4.z; Bs[lc + 3][lr] = b4.w;
        __syncthreads();
#pragma unroll
        for (int k = 0; k < BK; k++) {
            float ra[TM], rb[TN];
#pragma unroll
            for (int i = 0; i < TM; i++) ra[i] = As[k][ty * TM + i];
#pragma unroll
            for (int j = 0; j < TN; j++) rb[j] = Bs[k][tx * TN + j];
#pragma unroll
            for (int i = 0; i < TM; i++)
#pragma unroll
                for (int j = 0; j < TN; j++) acc[i][j] += ra[i] * rb[j];
        }
        __syncthreads();
    }

#pragma unroll
    for (int i = 0; i < TM; i++) {
        int m = bm * BM + ty * TM + i;
        float* Crow = C + (long)m * N + bn * BN + tx * TN;
#pragma unroll
        for (int j = 0; j < TN; j += 4) {
            float4 v;
            v.x = acc[i][j + 0] * alpha;
            v.y = acc[i][j + 1] * alpha;
            v.z = acc[i][j + 2] * alpha;
            v.w = acc[i][j + 3] * alpha;
            *(float4*)(Crow + j) = v;
        }
    }
}

// ---------------------------------------------------------------------------
// NN GEMM tile: C[m,n] = sum_k A[m,k] * B[k,n]
// A: [M,K] K-contiguous. B: [K,N] N-contiguous.
// ---------------------------------------------------------------------------
__device__ __forceinline__ void gemm_nn_tile(
    const float* __restrict__ A, const float* __restrict__ B,
    float* __restrict__ C,
    int N, int K, int Klim, int bm, int bn)
{
    __shared__ float As[BK][BM];
    __shared__ float Bs[BK][BN];

    const int tid = threadIdx.x;
    const int tx = tid % (BN / TN);
    const int ty = tid / (BN / TN);
    const int lrA = tid / 2;
    const int lcA = (tid % 2) * 4;
    const int lrB = tid / 32;          // k row 0..7
    const int lcB = (tid % 32) * 4;    // n col

    float acc[TM][TN];
#pragma unroll
    for (int i = 0; i < TM; i++)
#pragma unroll
        for (int j = 0; j < TN; j++) acc[i][j] = 0.0f;

    const float* Aptr = A + (long)(bm * BM + lrA) * K + lcA;
    const float* Bptr = B + (long)lrB * N + bn * BN + lcB;

    for (int k0 = 0; k0 < Klim; k0 += BK) {
        float4 a4 = *(const float4*)(Aptr + k0);
        float4 b4 = *(const float4*)(Bptr + (long)k0 * N);
        As[lcA + 0][lrA] = a4.x; As[lcA + 1][lrA] = a4.y;
        As[lcA + 2][lrA] = a4.z; As[lcA + 3][lrA] = a4.w;
        *(float4*)&Bs[lrB][lcB] = b4;
        __syncthreads();
#pragma unroll
        for (int k = 0; k < BK; k++) {
            float ra[TM], rb[TN];
#pragma unroll
            for (int i = 0; i < TM; i++) ra[i] = As[k][ty * TM + i];
#pragma unroll
            for (int j = 0; j < TN; j++) rb[j] = Bs[k][tx * TN + j];
#pragma unroll
            for (int i = 0; i < TM; i++)
#pragma unroll
                for (int j = 0; j < TN; j++) acc[i][j] += ra[i] * rb[j];
        }
        __syncthreads();
    }

#pragma unroll
    for (int i = 0; i < TM; i++) {
        int m = bm * BM + ty * TM + i;
        float* Crow = C + (long)m * N + bn * BN + tx * TN;
#pragma unroll
        for (int j = 0; j < TN; j += 4) {
            float4 v;
            v.x = acc[i][j + 0]; v.y = acc[i][j + 1];
            v.z = acc[i][j + 2]; v.w = acc[i][j + 3];
            *(float4*)(Crow + j) = v;
        }
    }
}

// ---------------------------------------------------------------------------
// Kernels
// ---------------------------------------------------------------------------

// QKV projection: [8192,1024] x [1024,1024]^T, grid.z selects Q/K/V
__global__ void qkv_kernel(const float* __restrict__ x,
                           const float* __restrict__ Wq,
                           const float* __restrict__ Wk,
                           const float* __restrict__ Wv)
{
    const float* W = (blockIdx.z == 0) ? Wq : (blockIdx.z == 1) ? Wk : Wv;
    float* out = (blockIdx.z == 0) ? g_q : (blockIdx.z == 1) ? g_k : g_v;
    gemm_tn_tile(x, W, out, DIM, DIM, DIM, 1.0f, blockIdx.y, blockIdx.x);
}

// S = scale * Q K^T per batch; skip fully-masked upper-triangular blocks
__global__ void qk_kernel()
{
    const int bx = blockIdx.x, by = blockIdx.y, b = blockIdx.z;
    if (bx > by) return;  // all columns in block > all rows -> masked
    const float* Q = g_q + (long)b * SEQ * DIM;
    const float* K = g_k + (long)b * SEQ * DIM;
    float* S = g_s + (long)b * SEQ * SEQ;
    gemm_tn_tile(Q, K, S, SEQ, DIM, DIM, SCALE, by, bx);
}

// Row-wise causal softmax; zero the masked tail so PV needs no mask
__global__ void softmax_kernel()
{
    const int row = blockIdx.x;             // 0..8191
    const int b = row >> 11;
    const int i = row & (SEQ - 1);
    float* S = g_s + (long)b * SEQ * SEQ + (long)i * SEQ;
    const int n = i + 1;
    const int tid = threadIdx.x;
    __shared__ float red[NTHREADS];

    float lmax = -1e30f;
    for (int j = tid; j < n; j += NTHREADS) lmax = fmaxf(lmax, S[j]);
    red[tid] = lmax; __syncthreads();
    for (int s = NTHREADS / 2; s > 0; s >>= 1) {
        if (tid < s) red[tid] = fmaxf(red[tid], red[tid + s]);
        __syncthreads();
    }
    const float m = red[0]; __syncthreads();

    float lsum = 0.0f;
    for (int j = tid; j < n; j += NTHREADS) {
        float e = __expf(S[j] - m);
        S[j] = e;
        lsum += e;
    }
    red[tid] = lsum; __syncthreads();
    for (int s = NTHREADS / 2; s > 0; s >>= 1) {
        if (tid < s) red[tid] += red[tid + s];
        __syncthreads();
    }
    const float inv = 1.0f / red[0];

    for (int j = tid; j < n; j += NTHREADS) S[j] *= inv;
    for (int j = n + tid; j < SEQ; j += NTHREADS) S[j] = 0.0f;
}

// out = P V per batch; K-loop truncated at block-row end (causal, P tail = 0)
__global__ void pv_kernel(float* __restrict__ out)
{
    const int bx = blockIdx.x, by = blockIdx.y, b = blockIdx.z;
    const float* P = g_s + (long)b * SEQ * SEQ;
    const float* V = g_v + (long)b * SEQ * DIM;
    float* O = out + (long)b * SEQ * DIM;
    const int Klim = (by + 1) * BM;   // rows in this block need k <= by*BM+127
    gemm_nn_tile(P, V, O, DIM, SEQ, Klim, by, bx);
}

// ---------------------------------------------------------------------------
extern "C" void kernel_launch(void* const* d_in, const int* in_sizes, int n_in,
                              void* d_out, int out_size)
{
    const float* x  = (const float*)d_in[0];
    const float* Wq = (const float*)d_in[1];
    const float* Wk = (const float*)d_in[2];
    const float* Wv = (const float*)d_in[3];
    float* out = (float*)d_out;

    dim3 g_qkv(DIM / BN, (BATCH * SEQ) / BM, 3);        // (8, 64, 3)
    qkv_kernel<<<g_qkv, NTHREADS>>>(x, Wq, Wk, Wv);

    dim3 g_qk(SEQ / BN, SEQ / BM, BATCH);               // (16, 16, 4)
    qk_kernel<<<g_qk, NTHREADS>>>();

    softmax_kernel<<<BATCH * SEQ, NTHREADS>>>();

    dim3 g_pv(DIM / BN, SEQ / BM, BATCH);               // (8, 16, 4)
    pv_kernel<<<g_pv, NTHREADS>>>(out);
}

// round 3
// speedup vs baseline: 2.3632x; 2.3632x over previous
#include <cuda_runtime.h>
#include <cstdint>

// Problem constants
#define BATCH 4
#define SEQ   2048
#define DIM   1024
#define SCALE 0.03125f   // 1024^-0.5

// GEMM tile config (tf32 mma.sync)
#define BM 128
#define BN 128
#define BK 16
#define SSTRIDE 20        // smem row stride in words (conflict-free for frag loads)
#define NTHREADS 256

// Scratch (device globals: allocation-free rule)
static __device__ float g_q[BATCH * SEQ * DIM];
static __device__ float g_k[BATCH * SEQ * DIM];
static __device__ float g_v[BATCH * SEQ * DIM];
static __device__ float g_vt[BATCH * DIM * SEQ];                // V^T per batch
static __device__ float g_s[(size_t)BATCH * SEQ * SEQ];

// ---------------------------------------------------------------------------
// tf32 helpers
// ---------------------------------------------------------------------------
__device__ __forceinline__ uint32_t f2tf32(float f) {
    uint32_t u;
    asm("cvt.rna.tf32.f32 %0, %1;" : "=r"(u) : "f"(f));
    return u;
}

__device__ __forceinline__ void mma_tf32(float* c, const uint32_t* a, const uint32_t* b) {
    asm volatile(
        "mma.sync.aligned.m16n8k8.row.col.f32.tf32.tf32.f32 "
        "{%0,%1,%2,%3}, {%4,%5,%6,%7}, {%8,%9}, {%0,%1,%2,%3};\n"
        : "+f"(c[0]), "+f"(c[1]), "+f"(c[2]), "+f"(c[3])
        : "r"(a[0]), "r"(a[1]), "r"(a[2]), "r"(a[3]),
          "r"(b[0]), "r"(b[1]));
}

// ---------------------------------------------------------------------------
// TN GEMM via tf32 tensor cores:
//   C[m,n] = alpha * sum_k A[m,k] * B[n,k]
// A: [M,K] row-major (K contiguous, lda). B: [N,K] row-major (K contiguous, ldb).
// 128x128 tile, 8 warps (2x4), warp tile 64x32 = 4x4 m16n8k8 MMAs.
// Double-buffered smem, register-prefetched global loads.
// ---------------------------------------------------------------------------
__device__ __forceinline__ void gemm_tn_mma(
    const float* __restrict__ A, int lda,
    const float* __restrict__ B, int ldb,
    float* __restrict__ C, int ldc,
    int Klim, float alpha, int bm, int bn)
{
    __shared__ uint32_t sA[2][BM][SSTRIDE];
    __shared__ uint32_t sB[2][BN][SSTRIDE];

    const int tid  = threadIdx.x;
    const int warp = tid >> 5;
    const int lane = tid & 31;
    const int wr = warp >> 2;        // 0..1  (warp row, 64 rows each)
    const int wc = warp & 3;         // 0..3  (warp col, 32 cols each)
    const int g  = lane >> 2;        // 0..7
    const int t  = lane & 3;         // 0..3

    // Loader mapping: each thread loads 2 float4 per operand.
    const int lrow = tid >> 1;           // 0..127
    const int lseg = (tid & 1) * 2;      // 0 or 2 (two segs each: lseg, lseg+1)

    const float* Aptr = A + (long)(bm * BM + lrow) * lda + lseg * 4;
    const float* Bptr = B + (long)(bn * BN + lrow) * ldb + lseg * 4;

    float acc[4][4][4];
#pragma unroll
    for (int i = 0; i < 4; i++)
#pragma unroll
        for (int j = 0; j < 4; j++)
#pragma unroll
            for (int r = 0; r < 4; r++) acc[i][j][r] = 0.0f;

    const int nIter = Klim / BK;

    float4 ra0, ra1, rb0, rb1;

    // Prologue: load tile 0 into regs, convert+store to buf 0.
    ra0 = *(const float4*)(Aptr);
    ra1 = *(const float4*)(Aptr + 4);
    rb0 = *(const float4*)(Bptr);
    rb1 = *(const float4*)(Bptr + 4);
    {
        uint4 ua0 = { f2tf32(ra0.x), f2tf32(ra0.y), f2tf32(ra0.z), f2tf32(ra0.w) };
        uint4 ua1 = { f2tf32(ra1.x), f2tf32(ra1.y), f2tf32(ra1.z), f2tf32(ra1.w) };
        uint4 ub0 = { f2tf32(rb0.x), f2tf32(rb0.y), f2tf32(rb0.z), f2tf32(rb0.w) };
        uint4 ub1 = { f2tf32(rb1.x), f2tf32(rb1.y), f2tf32(rb1.z), f2tf32(rb1.w) };
        *(uint4*)&sA[0][lrow][lseg * 4]     = ua0;
        *(uint4*)&sA[0][lrow][lseg * 4 + 4] = ua1;
        *(uint4*)&sB[0][lrow][lseg * 4]     = ub0;
        *(uint4*)&sB[0][lrow][lseg * 4 + 4] = ub1;
    }
    __syncthreads();

    int buf = 0;
    for (int it = 0; it < nIter; ++it) {
        const bool hasNext = (it + 1) < nIter;
        if (hasNext) {
            const int k0 = (it + 1) * BK;
            ra0 = *(const float4*)(Aptr + k0);
            ra1 = *(const float4*)(Aptr + k0 + 4);
            rb0 = *(const float4*)(Bptr + k0);
            rb1 = *(const float4*)(Bptr + k0 + 4);
        }

        // Compute on smem[buf]: 2 k-steps of 8.
#pragma unroll
        for (int ks = 0; ks < 2; ks++) {
            const int kk = ks * 8;
            uint32_t af[4][4], bf[4][2];
#pragma unroll
            for (int mt = 0; mt < 4; mt++) {
                const int m0 = wr * 64 + mt * 16;
                af[mt][0] = sA[buf][m0 + g][kk + t];
                af[mt][1] = sA[buf][m0 + g + 8][kk + t];
                af[mt][2] = sA[buf][m0 + g][kk + t + 4];
                af[mt][3] = sA[buf][m0 + g + 8][kk + t + 4];
            }
#pragma unroll
            for (int nt = 0; nt < 4; nt++) {
                const int n0 = wc * 32 + nt * 8;
                bf[nt][0] = sB[buf][n0 + g][kk + t];
                bf[nt][1] = sB[buf][n0 + g][kk + t + 4];
            }
#pragma unroll
            for (int mt = 0; mt < 4; mt++)
#pragma unroll
                for (int nt = 0; nt < 4; nt++)
                    mma_tf32(acc[mt][nt], af[mt], bf[nt]);
        }

        if (hasNext) {
            const int nb = buf ^ 1;
            uint4 ua0 = { f2tf32(ra0.x), f2tf32(ra0.y), f2tf32(ra0.z), f2tf32(ra0.w) };
            uint4 ua1 = { f2tf32(ra1.x), f2tf32(ra1.y), f2tf32(ra1.z), f2tf32(ra1.w) };
            uint4 ub0 = { f2tf32(rb0.x), f2tf32(rb0.y), f2tf32(rb0.z), f2tf32(rb0.w) };
            uint4 ub1 = { f2tf32(rb1.x), f2tf32(rb1.y), f2tf32(rb1.z), f2tf32(rb1.w) };
            *(uint4*)&sA[nb][lrow][lseg * 4]     = ua0;
            *(uint4*)&sA[nb][lrow][lseg * 4 + 4] = ua1;
            *(uint4*)&sB[nb][lrow][lseg * 4]     = ub0;
            *(uint4*)&sB[nb][lrow][lseg * 4 + 4] = ub1;
        }
        __syncthreads();
        buf ^= 1;
    }

    // Epilogue: scatter C fragments.
#pragma unroll
    for (int mt = 0; mt < 4; mt++) {
#pragma unroll
        for (int nt = 0; nt < 4; nt++) {
            const int m = bm * BM + wr * 64 + mt * 16 + g;
            const int n = bn * BN + wc * 32 + nt * 8 + 2 * t;
            float2 v0 = { acc[mt][nt][0] * alpha, acc[mt][nt][1] * alpha };
            float2 v1 = { acc[mt][nt][2] * alpha, acc[mt][nt][3] * alpha };
            *(float2*)&C[(long)m * ldc + n]       = v0;
            *(float2*)&C[(long)(m + 8) * ldc + n] = v1;
        }
    }
}

// ---------------------------------------------------------------------------
// Kernels
// ---------------------------------------------------------------------------

// QKV projection: [8192,1024] x W[1024,1024] (TN), grid.z selects Q/K/V
__global__ void __launch_bounds__(NTHREADS)
qkv_kernel(const float* __restrict__ x,
           const float* __restrict__ Wq,
           const float* __restrict__ Wk,
           const float* __restrict__ Wv)
{
    const float* W = (blockIdx.z == 0) ? Wq : (blockIdx.z == 1) ? Wk : Wv;
    float* out = (blockIdx.z == 0) ? g_q : (blockIdx.z == 1) ? g_k : g_v;
    gemm_tn_mma(x, DIM, W, DIM, out, DIM, DIM, 1.0f, blockIdx.y, blockIdx.x);
}

// Transpose V: g_v [b][t][d] -> g_vt [b][d][t]
__global__ void transpose_v_kernel()
{
    __shared__ float tile[32][33];
    const int b = blockIdx.z;
    const int d0 = blockIdx.x * 32;
    const int t0 = blockIdx.y * 32;
    const float* V  = g_v  + (long)b * SEQ * DIM;
    float*       VT = g_vt + (long)b * DIM * SEQ;
    const int tx = threadIdx.x, ty = threadIdx.y;
#pragma unroll
    for (int i = 0; i < 32; i += 8)
        tile[ty + i][tx] = V[(long)(t0 + ty + i) * DIM + d0 + tx];
    __syncthreads();
#pragma unroll
    for (int i = 0; i < 32; i += 8)
        VT[(long)(d0 + ty + i) * SEQ + t0 + tx] = tile[tx][ty + i];
}

// S = scale * Q K^T per batch (TN); skip fully-masked upper-triangular blocks
__global__ void __launch_bounds__(NTHREADS)
qk_kernel()
{
    const int bx = blockIdx.x, by = blockIdx.y, b = blockIdx.z;
    if (bx > by) return;  // all columns in block > all rows -> masked
    const float* Q = g_q + (long)b * SEQ * DIM;
    const float* K = g_k + (long)b * SEQ * DIM;
    float* S = g_s + (long)b * SEQ * SEQ;
    gemm_tn_mma(Q, DIM, K, DIM, S, SEQ, DIM, SCALE, by, bx);
}

// Row-wise causal softmax; zero the masked tail so PV needs no mask
__global__ void softmax_kernel()
{
    const int row = blockIdx.x;             // 0..8191
    const int b = row >> 11;
    const int i = row & (SEQ - 1);
    float* S = g_s + (long)b * SEQ * SEQ + (long)i * SEQ;
    const int n = i + 1;
    const int tid = threadIdx.x;
    __shared__ float red[NTHREADS];

    float lmax = -1e30f;
    for (int j = tid; j < n; j += NTHREADS) lmax = fmaxf(lmax, S[j]);
    red[tid] = lmax; __syncthreads();
    for (int s = NTHREADS / 2; s > 0; s >>= 1) {
        if (tid < s) red[tid] = fmaxf(red[tid], red[tid + s]);
        __syncthreads();
    }
    const float m = red[0]; __syncthreads();

    float lsum = 0.0f;
    for (int j = tid; j < n; j += NTHREADS) {
        float e = __expf(S[j] - m);
        S[j] = e;
        lsum += e;
    }
    red[tid] = lsum; __syncthreads();
    for (int s = NTHREADS / 2; s > 0; s >>= 1) {
        if (tid < s) red[tid] += red[tid + s];
        __syncthreads();
    }
    const float inv = 1.0f / red[0];

    for (int j = tid; j < n; j += NTHREADS) S[j] *= inv;
    for (int j = n + tid; j < SEQ; j += NTHREADS) S[j] = 0.0f;
}

// out = P V per batch = P[m,k] * VT[n,k] (TN); K truncated at causal block row end
__global__ void __launch_bounds__(NTHREADS)
pv_kernel(float* __restrict__ out)
{
    const int bx = blockIdx.x, by = blockIdx.y, b = blockIdx.z;
    const float* P  = g_s  + (long)b * SEQ * SEQ;
    const float* VT = g_vt + (long)b * DIM * SEQ;
    float* O = out + (long)b * SEQ * DIM;
    const int Klim = (by + 1) * BM;   // causal: rows in this block need k < (by+1)*128
    gemm_tn_mma(P, SEQ, VT, SEQ, O, DIM, Klim, 1.0f, by, bx);
}

// ---------------------------------------------------------------------------
extern "C" void kernel_launch(void* const* d_in, const int* in_sizes, int n_in,
                              void* d_out, int out_size)
{
    const float* x  = (const float*)d_in[0];
    const float* Wq = (const float*)d_in[1];
    const float* Wk = (const float*)d_in[2];
    const float* Wv = (const float*)d_in[3];
    float* out = (float*)d_out;

    dim3 g_qkv(DIM / BN, (BATCH * SEQ) / BM, 3);        // (8, 64, 3)
    qkv_kernel<<<g_qkv, NTHREADS>>>(x, Wq, Wk, Wv);

    dim3 g_tr(DIM / 32, SEQ / 32, BATCH);               // (32, 64, 4)
    transpose_v_kernel<<<g_tr, dim3(32, 8)>>>();

    dim3 g_qk(SEQ / BN, SEQ / BM, BATCH);               // (16, 16, 4)
    qk_kernel<<<g_qk, NTHREADS>>>();

    softmax_kernel<<<BATCH * SEQ, NTHREADS>>>();

    dim3 g_pv(DIM / BN, SEQ / BM, BATCH);               // (8, 16, 4)
    pv_kernel<<<g_pv, NTHREADS>>>(out);
}

// round 5
// speedup vs baseline: 3.1129x; 1.3172x over previous
#include <cuda_runtime.h>
#include <cstdint>

// Problem constants
#define BATCH 4
#define SEQ   2048
#define DIM   1024
#define SCALE 0.03125f   // 1024^-0.5

// GEMM tile config (legacy mma.sync tf32, cp.async multistage)
#define BM 128
#define BN 128
#define BK 16
#define STAGES 4
#define NTHREADS 128
#define ROWW 20                            // padded row stride (words); conflict-free
#define A_BYTES (BM * ROWW * 4)            // 10240
#define STAGE_BYTES (2 * A_BYTES)          // 20480 (A tile + B tile)
#define SMEM_TOTAL (STAGES * STAGE_BYTES)  // 81920

// Scratch (device globals: allocation-free rule)
static __device__ float g_q[BATCH * SEQ * DIM];
static __device__ float g_k[BATCH * SEQ * DIM];
static __device__ float g_v[BATCH * SEQ * DIM];
static __device__ float g_vt[BATCH * DIM * SEQ];
static __device__ float g_s[(size_t)BATCH * SEQ * SEQ];

// ---------------------------------------------------------------------------
// helpers
// ---------------------------------------------------------------------------
static __device__ __forceinline__ uint32_t smem_u32(const void* p) {
    uint32_t a;
    asm("{ .reg .u64 t; cvta.to.shared.u64 t, %1; cvt.u32.u64 %0, t; }" : "=r"(a) : "l"(p));
    return a;
}

static __device__ __forceinline__ uint32_t f2tf32(float f) {
    uint32_t u;
    asm("cvt.rna.tf32.f32 %0, %1;" : "=r"(u) : "f"(f));
    return u;
}

static __device__ __forceinline__ void mma_tf32(float* c, const uint32_t* a, const uint32_t* b) {
    asm volatile(
        "mma.sync.aligned.m16n8k8.row.col.f32.tf32.tf32.f32 "
        "{%0,%1,%2,%3}, {%4,%5,%6,%7}, {%8,%9}, {%0,%1,%2,%3};\n"
        : "+f"(c[0]), "+f"(c[1]), "+f"(c[2]), "+f"(c[3])
        : "r"(a[0]), "r"(a[1]), "r"(a[2]), "r"(a[3]),
          "r"(b[0]), "r"(b[1]));
}

static __device__ __forceinline__ void cp16(uint32_t dst, const void* src) {
    asm volatile("cp.async.ca.shared.global [%0], [%1], 16;" :: "r"(dst), "l"(src) : "memory");
}
static __device__ __forceinline__ void cp_commit() {
    asm volatile("cp.async.commit_group;" ::: "memory");
}
template <int N>
static __device__ __forceinline__ void cp_wait() {
    asm volatile("cp.async.wait_group %0;" :: "n"(N) : "memory");
}

// ---------------------------------------------------------------------------
// TN GEMM (tf32 mma.sync, 4-stage cp.async pipeline):
//   C[m,n] = alpha * sum_k A[m,k] * B[n,k]
// A: [M,K] K-contiguous (lda). B: [N,K] K-contiguous (ldb). Klim % BK == 0.
// 128x128 CTA tile, 4 warps (2x2), warp tile 64x64 = 4x8 m16n8k8 MMAs per k8.
// ---------------------------------------------------------------------------
static __device__ __forceinline__ void gemm_tc(
    const float* __restrict__ A, int lda,
    const float* __restrict__ B, int ldb,
    float* __restrict__ C, int ldc,
    int Klim, float alpha, int bm, int bn)
{
    extern __shared__ char smem[];
    const uint32_t sbase = smem_u32(smem);

    const int tid  = threadIdx.x;
    const int warp = tid >> 5;
    const int lane = tid & 31;
    const int wr = warp >> 1;          // 0..1: warp row (64 rows)
    const int wc = warp & 1;           // 0..1: warp col (64 cols)
    const int g  = lane >> 2;          // 0..7
    const int t  = lane & 3;           // 0..3

    // Loader mapping: thread covers rows (tid>>2)+32p, 16B col-segment (tid&3).
    const int lrow = tid >> 2;         // 0..31
    const int lseg = tid & 3;          // 0..3
    const float* Abase = A + (long)(bm * BM + lrow) * lda + lseg * 4;
    const float* Bbase = B + (long)(bn * BN + lrow) * ldb + lseg * 4;
    const uint32_t soff = (uint32_t)lrow * (ROWW * 4) + (uint32_t)lseg * 16;

    float acc[4][8][4];
#pragma unroll
    for (int i = 0; i < 4; i++)
#pragma unroll
        for (int j = 0; j < 8; j++)
#pragma unroll
            for (int r = 0; r < 4; r++) acc[i][j][r] = 0.0f;

    const int n = Klim / BK;

    // Stage issue: 4 cp.async per operand per thread (rows +0,+32,+64,+96).
#define ISSUE_STAGE(stage, itv)                                              \
    do {                                                                     \
        if ((itv) < n) {                                                     \
            const uint32_t sa = sbase + (uint32_t)(stage) * STAGE_BYTES + soff; \
            const uint32_t sb = sa + A_BYTES;                                \
            const float* ag = Abase + (long)(itv) * BK;                      \
            const float* bg = Bbase + (long)(itv) * BK;                      \
            _Pragma("unroll")                                                \
            for (int p = 0; p < 4; p++) {                                    \
                cp16(sa + p * 32 * (ROWW * 4), ag + (long)p * 32 * lda);     \
                cp16(sb + p * 32 * (ROWW * 4), bg + (long)p * 32 * ldb);     \
            }                                                                \
        }                                                                    \
        cp_commit();                                                         \
    } while (0)

#pragma unroll
    for (int s = 0; s < STAGES - 1; s++) ISSUE_STAGE(s, s);

    for (int it = 0; it < n; it++) {
        cp_wait<STAGES - 2>();
        __syncthreads();

        // Prefetch stage it+STAGES-1 into buffer (it-1)%STAGES (just freed).
        ISSUE_STAGE((it + STAGES - 1) % STAGES, it + STAGES - 1);

        const char* buf = smem + (size_t)(it % STAGES) * STAGE_BYTES;
        const float (*As)[ROWW] = (const float (*)[ROWW])(buf);
        const float (*Bs)[ROWW] = (const float (*)[ROWW])(buf + A_BYTES);

#pragma unroll
        for (int ks = 0; ks < 2; ks++) {
            const int kk = ks * 8;
            uint32_t af[4][4], bf[8][2];
#pragma unroll
            for (int mt = 0; mt < 4; mt++) {
                const int m0 = wr * 64 + mt * 16;
                af[mt][0] = f2tf32(As[m0 + g][kk + t]);
                af[mt][1] = f2tf32(As[m0 + g + 8][kk + t]);
                af[mt][2] = f2tf32(As[m0 + g][kk + t + 4]);
                af[mt][3] = f2tf32(As[m0 + g + 8][kk + t + 4]);
            }
#pragma unroll
            for (int nt = 0; nt < 8; nt++) {
                const int n0 = wc * 64 + nt * 8;
                bf[nt][0] = f2tf32(Bs[n0 + g][kk + t]);
                bf[nt][1] = f2tf32(Bs[n0 + g][kk + t + 4]);
            }
#pragma unroll
            for (int mt = 0; mt < 4; mt++)
#pragma unroll
                for (int nt = 0; nt < 8; nt++)
                    mma_tf32(acc[mt][nt], af[mt], bf[nt]);
        }
    }
#undef ISSUE_STAGE

    // Epilogue: scatter C fragments (coalesced float2 within each warp row).
#pragma unroll
    for (int mt = 0; mt < 4; mt++) {
#pragma unroll
        for (int nt = 0; nt < 8; nt++) {
            const int m  = bm * BM + wr * 64 + mt * 16 + g;
            const int nn = bn * BN + wc * 64 + nt * 8 + 2 * t;
            float2 v0 = { acc[mt][nt][0] * alpha, acc[mt][nt][1] * alpha };
            float2 v1 = { acc[mt][nt][2] * alpha, acc[mt][nt][3] * alpha };
            *(float2*)&C[(long)m * ldc + nn]       = v0;
            *(float2*)&C[(long)(m + 8) * ldc + nn] = v1;
        }
    }
}

// ---------------------------------------------------------------------------
// Kernels
// ---------------------------------------------------------------------------

__global__ void __launch_bounds__(NTHREADS, 2)
qkv_kernel(const float* __restrict__ x,
           const float* __restrict__ Wq,
           const float* __restrict__ Wk,
           const float* __restrict__ Wv)
{
    const float* W = (blockIdx.z == 0) ? Wq : (blockIdx.z == 1) ? Wk : Wv;
    float* out = (blockIdx.z == 0) ? g_q : (blockIdx.z == 1) ? g_k : g_v;
    gemm_tc(x, DIM, W, DIM, out, DIM, DIM, 1.0f, blockIdx.y, blockIdx.x);
}

__global__ void transpose_v_kernel()
{
    __shared__ float tile[32][33];
    const int b = blockIdx.z;
    const int d0 = blockIdx.x * 32;
    const int t0 = blockIdx.y * 32;
    const float* V  = g_v  + (long)b * SEQ * DIM;
    float*       VT = g_vt + (long)b * DIM * SEQ;
    const int tx = threadIdx.x, ty = threadIdx.y;
#pragma unroll
    for (int i = 0; i < 32; i += 8)
        tile[ty + i][tx] = V[(long)(t0 + ty + i) * DIM + d0 + tx];
    __syncthreads();
#pragma unroll
    for (int i = 0; i < 32; i += 8)
        VT[(long)(d0 + ty + i) * SEQ + t0 + tx] = tile[tx][ty + i];
}

__global__ void __launch_bounds__(NTHREADS, 2)
qk_kernel()
{
    const int bx = blockIdx.x, by = blockIdx.y, b = blockIdx.z;
    if (bx > by) return;  // fully-masked causal block
    const float* Q = g_q + (long)b * SEQ * DIM;
    const float* K = g_k + (long)b * SEQ * DIM;
    float* S = g_s + (long)b * SEQ * SEQ;
    gemm_tc(Q, DIM, K, DIM, S, SEQ, DIM, SCALE, by, bx);
}

__global__ void softmax_kernel()
{
    const int row = blockIdx.x;
    const int b = row >> 11;
    const int i = row & (SEQ - 1);
    float* S = g_s + (long)b * SEQ * SEQ + (long)i * SEQ;
    const int n = i + 1;
    const int tid = threadIdx.x;
    __shared__ float red[256];

    float lmax = -1e30f;
    for (int j = tid; j < n; j += 256) lmax = fmaxf(lmax, S[j]);
    red[tid] = lmax; __syncthreads();
    for (int s = 128; s > 0; s >>= 1) {
        if (tid < s) red[tid] = fmaxf(red[tid], red[tid + s]);
        __syncthreads();
    }
    const float m = red[0]; __syncthreads();

    float lsum = 0.0f;
    for (int j = tid; j < n; j += 256) {
        float e = __expf(S[j] - m);
        S[j] = e;
        lsum += e;
    }
    red[tid] = lsum; __syncthreads();
    for (int s = 128; s > 0; s >>= 1) {
        if (tid < s) red[tid] += red[tid + s];
        __syncthreads();
    }
    const float inv = 1.0f / red[0];

    for (int j = tid; j < n; j += 256) S[j] *= inv;
    for (int j = n + tid; j < SEQ; j += 256) S[j] = 0.0f;
}

__global__ void __launch_bounds__(NTHREADS, 2)
pv_kernel(float* __restrict__ out)
{
    const int bx = blockIdx.x, by = blockIdx.y, b = blockIdx.z;
    const float* P  = g_s  + (long)b * SEQ * SEQ;
    const float* VT = g_vt + (long)b * DIM * SEQ;
    float* O = out + (long)b * SEQ * DIM;
    const int Klim = (by + 1) * BM;   // causal truncation (P tail zeroed by softmax)
    gemm_tc(P, SEQ, VT, SEQ, O, DIM, Klim, 1.0f, by, bx);
}

// ---------------------------------------------------------------------------
extern "C" void kernel_launch(void* const* d_in, const int* in_sizes, int n_in,
                              void* d_out, int out_size)
{
    const float* x  = (const float*)d_in[0];
    const float* Wq = (const float*)d_in[1];
    const float* Wk = (const float*)d_in[2];
    const float* Wv = (const float*)d_in[3];
    float* out = (float*)d_out;

    // Idempotent, host-side attribute (no static guards; safe under capture).
    cudaFuncSetAttribute(qkv_kernel, cudaFuncAttributeMaxDynamicSharedMemorySize, SMEM_TOTAL);
    cudaFuncSetAttribute(qk_kernel,  cudaFuncAttributeMaxDynamicSharedMemorySize, SMEM_TOTAL);
    cudaFuncSetAttribute(pv_kernel,  cudaFuncAttributeMaxDynamicSharedMemorySize, SMEM_TOTAL);

    dim3 g_qkv(DIM / BN, (BATCH * SEQ) / BM, 3);        // (8, 64, 3)
    qkv_kernel<<<g_qkv, NTHREADS, SMEM_TOTAL>>>(x, Wq, Wk, Wv);

    dim3 g_tr(DIM / 32, SEQ / 32, BATCH);               // (32, 64, 4)
    transpose_v_kernel<<<g_tr, dim3(32, 8)>>>();

    dim3 g_qk(SEQ / BN, SEQ / BM, BATCH);               // (16, 16, 4)
    qk_kernel<<<g_qk, NTHREADS, SMEM_TOTAL>>>();

    softmax_kernel<<<BATCH * SEQ, 256>>>();

    dim3 g_pv(DIM / BN, SEQ / BM, BATCH);               // (8, 16, 4)
    pv_kernel<<<g_pv, NTHREADS, SMEM_TOTAL>>>(out);
}

// round 6
// speedup vs baseline: 7.0498x; 2.2647x over previous
#include <cuda_runtime.h>
#include <cuda_fp16.h>
#include <cstdint>

// Problem constants
#define BATCH 4
#define SEQ   2048
#define DIM   1024
#define SCALE 0.03125f   // 1024^-0.5

// GEMM tile config (fp16 mma.sync m16n8k16, cp.async multistage)
#define BM 128
#define BN 128
#define BK 32                              // halfs per k-chunk (64B rows)
#define STAGES 4
#define NTHREADS 128
#define ROWB 80                            // padded row bytes (64 data + 16 pad); 16B-aligned rows
#define A_BYTES (BM * ROWB)                // 10240
#define STAGE_BYTES (2 * A_BYTES)          // 20480
#define SMEM_TOTAL (STAGES * STAGE_BYTES)  // 81920

// Scratch (device globals: allocation-free rule)
static __device__ __half g_xh[BATCH * SEQ * DIM];
static __device__ __half g_wh[3 * DIM * DIM];
static __device__ __half g_qh[BATCH * SEQ * DIM];
static __device__ __half g_kh[BATCH * SEQ * DIM];
static __device__ __half g_vh[BATCH * SEQ * DIM];
static __device__ __half g_vth[BATCH * DIM * SEQ];
static __device__ float  g_s[(size_t)BATCH * SEQ * SEQ];
static __device__ __half g_ph[(size_t)BATCH * SEQ * SEQ];

// ---------------------------------------------------------------------------
// helpers
// ---------------------------------------------------------------------------
static __device__ __forceinline__ uint32_t smem_u32(const void* p) {
    uint32_t a;
    asm("{ .reg .u64 t; cvta.to.shared.u64 t, %1; cvt.u32.u64 %0, t; }" : "=r"(a) : "l"(p));
    return a;
}

static __device__ __forceinline__ void ldsm_x4(uint32_t* r, uint32_t addr) {
    asm volatile("ldmatrix.sync.aligned.m8n8.x4.shared.b16 {%0,%1,%2,%3}, [%4];"
                 : "=r"(r[0]), "=r"(r[1]), "=r"(r[2]), "=r"(r[3]) : "r"(addr));
}

static __device__ __forceinline__ void mma_f16(float* c, const uint32_t* a, const uint32_t* b) {
    asm volatile(
        "mma.sync.aligned.m16n8k16.row.col.f32.f16.f16.f32 "
        "{%0,%1,%2,%3}, {%4,%5,%6,%7}, {%8,%9}, {%0,%1,%2,%3};\n"
        : "+f"(c[0]), "+f"(c[1]), "+f"(c[2]), "+f"(c[3])
        : "r"(a[0]), "r"(a[1]), "r"(a[2]), "r"(a[3]),
          "r"(b[0]), "r"(b[1]));
}

static __device__ __forceinline__ void cp16(uint32_t dst, const void* src) {
    asm volatile("cp.async.ca.shared.global [%0], [%1], 16;" :: "r"(dst), "l"(src) : "memory");
}
static __device__ __forceinline__ void cp_commit() {
    asm volatile("cp.async.commit_group;" ::: "memory");
}
template <int N>
static __device__ __forceinline__ void cp_wait() {
    asm volatile("cp.async.wait_group %0;" :: "n"(N) : "memory");
}

// ---------------------------------------------------------------------------
// TN GEMM (fp16 mma.sync m16n8k16, 4-stage cp.async pipeline):
//   C[m,n] = alpha * sum_k A[m,k] * B[n,k]   (fp32 accumulation)
// A: [M,K] half, K-contiguous (lda). B: [N,K] half, K-contiguous (ldb).
// Klim % BK == 0. 128x128 CTA tile, 4 warps (2x2), warp tile 64x64.
// OutT: float or __half.
// ---------------------------------------------------------------------------
template <typename OutT>
static __device__ __forceinline__ void gemm_h(
    const __half* __restrict__ A, int lda,
    const __half* __restrict__ B, int ldb,
    OutT* __restrict__ C, int ldc,
    int Klim, float alpha, int bm, int bn)
{
    extern __shared__ char smem[];
    const uint32_t sbase = smem_u32(smem);

    const int tid  = threadIdx.x;
    const int warp = tid >> 5;
    const int lane = tid & 31;
    const int wr = warp >> 1;          // warp row (64 rows)
    const int wc = warp & 1;           // warp col (64 cols)
    const int g  = lane >> 2;
    const int t  = lane & 3;

    // Staging: thread covers rows lrow+{0,32,64,96}, 16B segment lseg.
    const int lrow = tid >> 2;         // 0..31
    const int lseg = tid & 3;          // 0..3
    const __half* Abase = A + (long)(bm * BM + lrow) * lda + lseg * 8;
    const __half* Bbase = B + (long)(bn * BN + lrow) * ldb + lseg * 8;
    const uint32_t soff = (uint32_t)lrow * ROWB + (uint32_t)lseg * 16;

    // ldmatrix per-lane byte offsets (within a stage buffer).
    // A x4: matrices (m0k0),(m8k0),(m0k8),(m8k8): row = m0+(lane&15), col8 = (lane>>4)*8 halfs
    const uint32_t aoff = (uint32_t)(wr * 64 + (lane & 15)) * ROWB + (uint32_t)(lane >> 4) * 16;
    // B x4 (two n-tiles): (n0k0),(n0k8),(n8k0),(n8k8):
    //   row = n0+(lane&7)+((lane&16)?8:0), col8 = ((lane>>3)&1)*8 halfs
    const uint32_t boff = A_BYTES
        + (uint32_t)(wc * 64 + (lane & 7) + ((lane & 16) ? 8 : 0)) * ROWB
        + (uint32_t)((lane >> 3) & 1) * 16;

    float acc[4][8][4];
#pragma unroll
    for (int i = 0; i < 4; i++)
#pragma unroll
        for (int j = 0; j < 8; j++)
#pragma unroll
            for (int r = 0; r < 4; r++) acc[i][j][r] = 0.0f;

    const int n = Klim / BK;

#define ISSUE_STAGE(stage, itv)                                                 \
    do {                                                                        \
        if ((itv) < n) {                                                        \
            const uint32_t sa = sbase + (uint32_t)(stage) * STAGE_BYTES + soff; \
            const uint32_t sb = sa + A_BYTES;                                   \
            const __half* ag = Abase + (long)(itv) * BK;                        \
            const __half* bg = Bbase + (long)(itv) * BK;                        \
            _Pragma("unroll")                                                   \
            for (int p = 0; p < 4; p++) {                                       \
                cp16(sa + p * 32 * ROWB, ag + (long)p * 32 * lda);              \
                cp16(sb + p * 32 * ROWB, bg + (long)p * 32 * ldb);              \
            }                                                                   \
        }                                                                       \
        cp_commit();                                                            \
    } while (0)

#pragma unroll
    for (int s = 0; s < STAGES - 1; s++) ISSUE_STAGE(s, s);

    for (int it = 0; it < n; it++) {
        cp_wait<STAGES - 2>();
        __syncthreads();

        ISSUE_STAGE((it + STAGES - 1) % STAGES, it + STAGES - 1);

        const uint32_t sb = sbase + (uint32_t)(it % STAGES) * STAGE_BYTES;

#pragma unroll
        for (int ks = 0; ks < 2; ks++) {
            const uint32_t kkB = (uint32_t)ks * 32;   // k16 halfs = 32 bytes
            uint32_t af[4][4], bf[8][2];
#pragma unroll
            for (int mt = 0; mt < 4; mt++)
                ldsm_x4(af[mt], sb + aoff + (uint32_t)mt * 16 * ROWB + kkB);
#pragma unroll
            for (int pr = 0; pr < 4; pr++) {
                uint32_t r[4];
                ldsm_x4(r, sb + boff + (uint32_t)pr * 16 * ROWB + kkB);
                bf[2 * pr][0]     = r[0]; bf[2 * pr][1]     = r[1];
                bf[2 * pr + 1][0] = r[2]; bf[2 * pr + 1][1] = r[3];
            }
#pragma unroll
            for (int mt = 0; mt < 4; mt++)
#pragma unroll
                for (int nt = 0; nt < 8; nt++)
                    mma_f16(acc[mt][nt], af[mt], bf[nt]);
        }
    }
#undef ISSUE_STAGE

    // Epilogue: c-frag m16n8 layout (c0,c1 @ row g; c2,c3 @ row g+8; cols 2t,2t+1)
#pragma unroll
    for (int mt = 0; mt < 4; mt++) {
#pragma unroll
        for (int nt = 0; nt < 8; nt++) {
            const int m  = bm * BM + wr * 64 + mt * 16 + g;
            const int nn = bn * BN + wc * 64 + nt * 8 + 2 * t;
            if constexpr (sizeof(OutT) == 4) {
                float2 v0 = { acc[mt][nt][0] * alpha, acc[mt][nt][1] * alpha };
                float2 v1 = { acc[mt][nt][2] * alpha, acc[mt][nt][3] * alpha };
                *(float2*)&((float*)C)[(long)m * ldc + nn]       = v0;
                *(float2*)&((float*)C)[(long)(m + 8) * ldc + nn] = v1;
            } else {
                __half2 h0 = __floats2half2_rn(acc[mt][nt][0] * alpha, acc[mt][nt][1] * alpha);
                __half2 h1 = __floats2half2_rn(acc[mt][nt][2] * alpha, acc[mt][nt][3] * alpha);
                *(__half2*)&((__half*)C)[(long)m * ldc + nn]       = h0;
                *(__half2*)&((__half*)C)[(long)(m + 8) * ldc + nn] = h1;
            }
        }
    }
}

// ---------------------------------------------------------------------------
// Kernels
// ---------------------------------------------------------------------------

// fp32 -> fp16 convert: x
__global__ void convx_kernel(const float* __restrict__ src)
{
    const int i = blockIdx.x * blockDim.x + threadIdx.x;
    const int n4 = BATCH * SEQ * DIM / 4;
    if (i < n4) {
        float4 v = ((const float4*)src)[i];
        ((__half2*)g_xh)[2 * i]     = __floats2half2_rn(v.x, v.y);
        ((__half2*)g_xh)[2 * i + 1] = __floats2half2_rn(v.z, v.w);
    }
}

// fp32 -> fp16 convert: Wq/Wk/Wv (grid.z selects)
__global__ void convw_kernel(const float* __restrict__ Wq,
                             const float* __restrict__ Wk,
                             const float* __restrict__ Wv)
{
    const float* src = (blockIdx.z == 0) ? Wq : (blockIdx.z == 1) ? Wk : Wv;
    __half* dst = g_wh + (size_t)blockIdx.z * DIM * DIM;
    const int i = blockIdx.x * blockDim.x + threadIdx.x;
    const int n4 = DIM * DIM / 4;
    if (i < n4) {
        float4 v = ((const float4*)src)[i];
        ((__half2*)dst)[2 * i]     = __floats2half2_rn(v.x, v.y);
        ((__half2*)dst)[2 * i + 1] = __floats2half2_rn(v.z, v.w);
    }
}

__global__ void __launch_bounds__(NTHREADS, 2)
qkv_kernel()
{
    const __half* W = g_wh + (size_t)blockIdx.z * DIM * DIM;
    __half* out = (blockIdx.z == 0) ? g_qh : (blockIdx.z == 1) ? g_kh : g_vh;
    gemm_h<__half>(g_xh, DIM, W, DIM, out, DIM, DIM, 1.0f, blockIdx.y, blockIdx.x);
}

__global__ void transpose_v_kernel()
{
    __shared__ unsigned short tile[32][34];   // stride 34 (gcd(17,32)=1 -> conflict-free cols)
    const int b = blockIdx.z;
    const int d0 = blockIdx.x * 32;
    const int t0 = blockIdx.y * 32;
    const unsigned short* V = (const unsigned short*)(g_vh + (long)b * SEQ * DIM);
    unsigned short* VT = (unsigned short*)(g_vth + (long)b * DIM * SEQ);
    const int tx = threadIdx.x, ty = threadIdx.y;
#pragma unroll
    for (int i = 0; i < 32; i += 8)
        tile[ty + i][tx] = V[(long)(t0 + ty + i) * DIM + d0 + tx];
    __syncthreads();
#pragma unroll
    for (int i = 0; i < 32; i += 8)
        VT[(long)(d0 + ty + i) * SEQ + t0 + tx] = tile[tx][ty + i];
}

__global__ void __launch_bounds__(NTHREADS, 2)
qk_kernel()
{
    const int bx = blockIdx.x, by = blockIdx.y, b = blockIdx.z;
    if (bx > by) return;  // fully-masked causal block
    const __half* Q = g_qh + (long)b * SEQ * DIM;
    const __half* K = g_kh + (long)b * SEQ * DIM;
    float* S = g_s + (long)b * SEQ * SEQ;
    gemm_h<float>(Q, DIM, K, DIM, S, SEQ, DIM, SCALE, by, bx);
}

// Causal softmax: read fp32 S, write fp16 P (zero tail). S not written back.
__global__ void softmax_kernel()
{
    const int row = blockIdx.x;
    const int b = row >> 11;
    const int i = row & (SEQ - 1);
    const float* S = g_s + (long)b * SEQ * SEQ + (long)i * SEQ;
    __half* P = g_ph + (long)b * SEQ * SEQ + (long)i * SEQ;
    const int n = i + 1;
    const int tid = threadIdx.x;
    __shared__ float red[256];

    float lmax = -1e30f;
    for (int j = tid; j < n; j += 256) lmax = fmaxf(lmax, S[j]);
    red[tid] = lmax; __syncthreads();
    for (int s = 128; s > 0; s >>= 1) {
        if (tid < s) red[tid] = fmaxf(red[tid], red[tid + s]);
        __syncthreads();
    }
    const float m = red[0]; __syncthreads();

    float lsum = 0.0f;
    for (int j = tid; j < n; j += 256) lsum += __expf(S[j] - m);
    red[tid] = lsum; __syncthreads();
    for (int s = 128; s > 0; s >>= 1) {
        if (tid < s) red[tid] += red[tid + s];
        __syncthreads();
    }
    const float inv = 1.0f / red[0];

    for (int j = tid; j < n; j += 256) P[j] = __float2half(__expf(S[j] - m) * inv);
    for (int j = n + tid; j < SEQ; j += 256) P[j] = __float2half(0.0f);
}

__global__ void __launch_bounds__(NTHREADS, 2)
pv_kernel(float* __restrict__ out)
{
    const int bx = blockIdx.x, by = blockIdx.y, b = blockIdx.z;
    const __half* P  = g_ph  + (long)b * SEQ * SEQ;
    const __half* VT = g_vth + (long)b * DIM * SEQ;
    float* O = out + (long)b * SEQ * DIM;
    const int Klim = (by + 1) * BM;   // causal truncation (P tail zeroed)
    gemm_h<float>(P, SEQ, VT, SEQ, O, DIM, Klim, 1.0f, by, bx);
}

// ---------------------------------------------------------------------------
extern "C" void kernel_launch(void* const* d_in, const int* in_sizes, int n_in,
                              void* d_out, int out_size)
{
    const float* x  = (const float*)d_in[0];
    const float* Wq = (const float*)d_in[1];
    const float* Wk = (const float*)d_in[2];
    const float* Wv = (const float*)d_in[3];
    float* out = (float*)d_out;

    cudaFuncSetAttribute(qkv_kernel, cudaFuncAttributeMaxDynamicSharedMemorySize, SMEM_TOTAL);
    cudaFuncSetAttribute(qk_kernel,  cudaFuncAttributeMaxDynamicSharedMemorySize, SMEM_TOTAL);
    cudaFuncSetAttribute(pv_kernel,  cudaFuncAttributeMaxDynamicSharedMemorySize, SMEM_TOTAL);

    convx_kernel<<<(BATCH * SEQ * DIM / 4 + 255) / 256, 256>>>(x);
    convw_kernel<<<dim3(DIM * DIM / 4 / 256, 1, 3), 256>>>(Wq, Wk, Wv);

    dim3 g_qkv(DIM / BN, (BATCH * SEQ) / BM, 3);        // (8, 64, 3)
    qkv_kernel<<<g_qkv, NTHREADS, SMEM_TOTAL>>>();

    dim3 g_tr(DIM / 32, SEQ / 32, BATCH);               // (32, 64, 4)
    transpose_v_kernel<<<g_tr, dim3(32, 8)>>>();

    dim3 g_qk(SEQ / BN, SEQ / BM, BATCH);               // (16, 16, 4)
    qk_kernel<<<g_qk, NTHREADS, SMEM_TOTAL>>>();

    softmax_kernel<<<BATCH * SEQ, 256>>>();

    dim3 g_pv(DIM / BN, SEQ / BM, BATCH);               // (8, 16, 4)
    pv_kernel<<<g_pv, NTHREADS, SMEM_TOTAL>>>(out);
}